// round 3
// baseline (speedup 1.0000x reference)
#include <cuda_runtime.h>

// SpectralConv1d via pruned "cas-FFT" butterflies (the reference fht1d is a
// radix-2 DIT recursion with cas twiddles, NOT the true DHT — we replicate it
// exactly as a linear operator).
//
// Pipeline:
//  1) forward:  per (b,i) row, 12-level butterfly, last 6 levels pruned to k<64
//  2) mix:      Z[b,o,m] = sum_i Y[b,i,m]*We[i,o,m] + Y[b,i,-m]*Wo[i,o,m]
//               with We/Wo = 0.5*(w +/- w_neg);  (1/4096 folded here)
//  3) inverse:  zero-padded spectrum -> bottom 6 levels collapse to a
//               broadcast init buf[p+64k]=z[p], then 6 full butterfly levels.

#define NN     4096
#define MODES  64
#define BATCH  64
#define CH     128
#define ROWS   (BATCH * CH)   // 8192

__device__ float g_CAS[2048];             // cas(2*pi*j/4096), j<2048
__device__ float g_Y[MODES * ROWS];       // [m][row=b*128+i]
__device__ float g_Z[ROWS * MODES];       // [row=b*128+o][m]  (already /4096)
__device__ float g_We[MODES * CH * CH];   // [m][i][o]
__device__ float g_Wo[MODES * CH * CH];   // [m][i][o]

__global__ void build_cas_kernel() {
    int j = blockIdx.x * blockDim.x + threadIdx.x;
    if (j < 2048) {
        float s, c;
        sincospif((float)j * (1.0f / 2048.0f), &s, &c);  // angle = pi*j/2048
        g_CAS[j] = c + s;
    }
}

// weights1: (i, o, m) row-major -> We/Wo in [m][i][o]
__global__ void build_wewo_kernel(const float* __restrict__ w1) {
    int t = blockIdx.x * blockDim.x + threadIdx.x;
    if (t >= MODES * CH * CH) return;
    int m   = t >> 14;          // /16384
    int rem = t & 16383;
    int i   = rem >> 7;
    int o   = rem & 127;
    int mn  = (MODES - m) & (MODES - 1);
    float a = w1[i * (CH * MODES) + o * MODES + m];
    float b = w1[i * (CH * MODES) + o * MODES + mn];
    g_We[t] = 0.5f * (a + b);
    g_Wo[t] = 0.5f * (a - b);
}

// Forward: one block per (b,i) row. Layout at depth t: addr = p + (k << t).
__global__ __launch_bounds__(256) void forward_kernel(const float* __restrict__ x) {
    __shared__ float bufA[NN];
    __shared__ float bufB[NN];
    __shared__ float cas_s[2048];
    int tid = threadIdx.x;
    int row = blockIdx.x;

    const float4* xr = (const float4*)(x + (size_t)row * NN);
    float4* a4 = (float4*)bufA;
    for (int v = tid; v < NN / 4; v += 256) a4[v] = xr[v];
    for (int j = tid; j < 2048; j += 256) cas_s[j] = g_CAS[j];
    __syncthreads();

    float* src = bufA;
    float* dst = bufB;

    // Full levels t = 11..6: 2048 pairs each.
    #pragma unroll
    for (int t = 11; t >= 6; --t) {
        for (int i = tid; i < 2048; i += 256) {
            int p  = i & ((1 << t) - 1);
            int kt = i >> t;
            float a = src[p + (kt << (t + 1))];
            float b = src[p + (1 << t) + (kt << (t + 1))];
            float c = cas_s[kt << t];
            dst[p + (kt << t)]        = fmaf(c, b, a);
            dst[p + (kt << t) + 2048] = fmaf(-c, b, a);
        }
        float* tmp = src; src = dst; dst = tmp;
        __syncthreads();
    }

    // Pruned levels t = 5..0: keep only k < 64 (sign always +, k < n_t/2).
    #pragma unroll
    for (int t = 5; t >= 0; --t) {
        int count = MODES << t;
        for (int i = tid; i < count; i += 256) {
            int p = i & ((1 << t) - 1);
            int k = i >> t;
            dst[p + (k << t)] =
                fmaf(cas_s[k << t], src[p + (1 << t) + (k << (t + 1))],
                     src[p + (k << (t + 1))]);
        }
        float* tmp = src; src = dst; dst = tmp;
        __syncthreads();
    }

    if (tid < MODES) g_Y[tid * ROWS + row] = src[tid];
}

// Mix: grid = 128 blocks (64 modes x 2 batch-halves), 512 threads.
__global__ __launch_bounds__(512) void mix_kernel() {
    __shared__ float Ys[32 * CH];
    __shared__ float Yn[32 * CH];
    int m    = blockIdx.x >> 1;
    int half = blockIdx.x & 1;
    int mn   = (MODES - m) & (MODES - 1);
    int tid  = threadIdx.x;
    int base = half * 4096;  // rows covered: [half*32, half*32+32) batches x 128 ch

    for (int idx = tid; idx < 4096; idx += 512) {
        Ys[idx] = g_Y[m * ROWS + base + idx];
        Yn[idx] = g_Y[mn * ROWS + base + idx];
    }
    __syncthreads();

    int o  = tid & 127;
    int bg = tid >> 7;  // 0..3, each covers 8 local batches
    float acc[8];
    #pragma unroll
    for (int bb = 0; bb < 8; ++bb) acc[bb] = 0.0f;

    const float* Wem = g_We + (size_t)m * CH * CH;
    const float* Wom = g_Wo + (size_t)m * CH * CH;
    for (int i = 0; i < CH; ++i) {
        float we = Wem[i * CH + o];
        float wo = Wom[i * CH + o];
        #pragma unroll
        for (int bb = 0; bb < 8; ++bb) {
            int l = bg * 8 + bb;
            acc[bb] = fmaf(Ys[l * CH + i], we, acc[bb]);
            acc[bb] = fmaf(Yn[l * CH + i], wo, acc[bb]);
        }
    }

    const float inv = 1.0f / 4096.0f;
    #pragma unroll
    for (int bb = 0; bb < 8; ++bb) {
        int b = half * 32 + bg * 8 + bb;
        g_Z[((size_t)(b * CH + o)) * MODES + m] = acc[bb] * inv;
    }
}

// Inverse: one block per (b,o) row. Init = broadcast (fht64 of delta = ones),
// then 6 full butterfly levels (t = 5..0).
__global__ __launch_bounds__(256) void inverse_kernel(float* __restrict__ out) {
    __shared__ float bufA[NN];
    __shared__ float bufB[NN];
    __shared__ float cas_s[2048];
    __shared__ float zb[MODES];
    int tid = threadIdx.x;
    int row = blockIdx.x;

    for (int j = tid; j < 2048; j += 256) cas_s[j] = g_CAS[j];
    if (tid < MODES) zb[tid] = g_Z[(size_t)row * MODES + tid];
    __syncthreads();

    for (int addr = tid; addr < NN; addr += 256) bufA[addr] = zb[addr & 63];
    __syncthreads();

    float* src = bufA;
    float* dst = bufB;
    #pragma unroll
    for (int t = 5; t >= 0; --t) {
        for (int i = tid; i < 2048; i += 256) {
            int p  = i & ((1 << t) - 1);
            int kt = i >> t;
            float a = src[p + (kt << (t + 1))];
            float b = src[p + (1 << t) + (kt << (t + 1))];
            float c = cas_s[kt << t];
            dst[p + (kt << t)]        = fmaf(c, b, a);
            dst[p + (kt << t) + 2048] = fmaf(-c, b, a);
        }
        float* tmp = src; src = dst; dst = tmp;
        __syncthreads();
    }

    float4* o4 = (float4*)(out + (size_t)row * NN);
    const float4* s4 = (const float4*)src;
    for (int v = tid; v < NN / 4; v += 256) o4[v] = s4[v];
}

extern "C" void kernel_launch(void* const* d_in, const int* in_sizes, int n_in,
                              void* d_out, int out_size) {
    const float* x  = (const float*)d_in[0];
    const float* w1 = (const float*)d_in[1];
    float* out = (float*)d_out;

    build_cas_kernel<<<8, 256>>>();
    build_wewo_kernel<<<(MODES * CH * CH + 511) / 512, 512>>>(w1);
    forward_kernel<<<ROWS, 256>>>(x);
    mix_kernel<<<MODES * 2, 512>>>();
    inverse_kernel<<<ROWS, 256>>>(out);
}

// round 4
// speedup vs baseline: 1.0729x; 1.0729x over previous
#include <cuda_runtime.h>

// SpectralConv1d via pruned cas-FFT, register-resident butterflies.
// Stockham level rule: level t pairs addresses differing in bit t, writes
// pairs differing in bit 11; bits t+1..11 shift down one.
//
// forward: levels 11..8 in regs (const twiddles) -> exchange ->
//          levels 7..5 in regs -> pruned smem loop t=4..0 -> Y[k<64]
// mix:     Z[b,o,m] = sum_i Y[m]*We + Y[-m]*Wo  (1/4096 folded)
// inverse: broadcast init -> levels 5..3 regs -> swizzled exchange ->
//          levels 2..0 regs -> float4 store via smem staging

#define NN     4096
#define MODES  64
#define BATCH  64
#define CH     128
#define ROWS   (BATCH * CH)   // 8192

#define SQ2   1.41421356237309515f
#define C256  1.30656296487637653f   // cas(pi/8)
#define C1280 0.54119610014619698f   // cas(5pi/8)

__device__ float g_CAS[2048];             // cas(2*pi*j/4096)
__device__ float g_Y[MODES * ROWS];       // [m][row]
__device__ float g_Z[ROWS * MODES];       // [row][m] (already /4096)
__device__ float g_We[MODES * CH * CH];   // [m][i][o]
__device__ float g_Wo[MODES * CH * CH];   // [m][i][o]

__global__ void build_cas_kernel() {
    int j = blockIdx.x * blockDim.x + threadIdx.x;
    if (j < 2048) {
        float s, c;
        sincospif((float)j * (1.0f / 2048.0f), &s, &c);
        g_CAS[j] = c + s;
    }
}

__global__ void build_wewo_kernel(const float* __restrict__ w1) {
    int t = blockIdx.x * blockDim.x + threadIdx.x;
    if (t >= MODES * CH * CH) return;
    int m   = t >> 14;
    int rem = t & 16383;
    int i   = rem >> 7;
    int o   = rem & 127;
    int mn  = (MODES - m) & (MODES - 1);
    float a = w1[i * (CH * MODES) + o * MODES + m];
    float b = w1[i * (CH * MODES) + o * MODES + mn];
    g_We[t] = 0.5f * (a + b);   // [m][i][o]
    g_Wo[t] = 0.5f * (a - b);
}

__device__ __forceinline__ int brev4(int r) {
    return ((r & 1) << 3) | ((r & 2) << 1) | ((r & 4) >> 1) | ((r & 8) >> 3);
}

// ---------------- forward ----------------
__global__ __launch_bounds__(256) void forward_kernel(const float* __restrict__ x) {
    __shared__ float buf[4096];
    __shared__ float cas1k[1024];
    __shared__ float cas32s[64];
    int h = threadIdx.x, row = blockIdx.x;

    for (int j = h; j < 1024; j += 256) cas1k[j] = g_CAS[j];
    if (h < 64) cas32s[h] = g_CAS[h << 5];

    const float* xr = x + (size_t)row * NN;
    float v[16];
    #pragma unroll
    for (int r = 0; r < 16; r++) v[r] = xr[h + (r << 8)];

    // stage 1: t=11 (tw=1), t=10 (tw=1), t=9, t=8 — all const twiddles
    #pragma unroll
    for (int r = 0; r < 8; r++) { float a = v[r], b = v[r + 8]; v[r] = a + b; v[r + 8] = a - b; }
    #pragma unroll
    for (int r = 0; r < 16; r++) if (!(r & 4)) { float a = v[r], b = v[r + 4]; v[r] = a + b; v[r + 4] = a - b; }
    {
        const float TW9[4] = {1.f, SQ2, 1.f, 0.f};
        #pragma unroll
        for (int r = 0; r < 16; r++) if (!(r & 2)) {
            int kt = ((r >> 3) & 1) | (((r >> 2) & 1) << 1);
            float w = TW9[kt], a = v[r], b = v[r + 2];
            v[r] = fmaf(w, b, a); v[r + 2] = fmaf(-w, b, a);
        }
    }
    {
        const float TW8[8] = {1.f, C256, SQ2, C256, 1.f, C1280, 0.f, -C1280};
        #pragma unroll
        for (int r = 0; r < 16; r += 2) {
            int kt = ((r >> 3) & 1) | (((r >> 2) & 1) << 1) | (((r >> 1) & 1) << 2);
            float w = TW8[kt], a = v[r], b = v[r + 1];
            v[r] = fmaf(w, b, a); v[r + 1] = fmaf(-w, b, a);
        }
    }
    // exchange: depth-8 layout, thread h owns addr = h + 256*brev4(r)
    #pragma unroll
    for (int r = 0; r < 16; r++) buf[h + (brev4(r) << 8)] = v[r];
    __syncthreads();

    // stage 2: thread owns free bits {5,6,7,11}; fixed {0..4}=h[0:5], {8,9,10}=h[5:8]
    int hi3 = h >> 5;
    int base = (h & 31) + (hi3 << 8);
    float u[16];
    #pragma unroll
    for (int r = 0; r < 16; r++) u[r] = buf[base + ((r & 7) << 5) + ((r & 8) << 8)];
    // t=7: kt = hi3 + 8*rb3
    #pragma unroll
    for (int r = 0; r < 16; r++) if (!(r & 4)) {
        float w = cas32s[(hi3 + (r & 8)) << 2];
        float a = u[r], b = u[r + 4];
        u[r] = fmaf(w, b, a); u[r + 4] = fmaf(-w, b, a);
    }
    // t=6: kt = hi3 + 8*rb3 + 16*rb2
    #pragma unroll
    for (int r = 0; r < 16; r++) if (!(r & 2)) {
        float w = cas32s[(hi3 + (r & 8) + ((r & 4) << 2)) << 1];
        float a = u[r], b = u[r + 2];
        u[r] = fmaf(w, b, a); u[r + 2] = fmaf(-w, b, a);
    }
    // t=5: kt = hi3 + 8*rb3 + 16*rb2 + 32*rb1
    #pragma unroll
    for (int r = 0; r < 16; r += 2) {
        float w = cas32s[hi3 + (r & 8) + ((r & 4) << 2) + ((r & 2) << 4)];
        float a = u[r], b = u[r + 1];
        u[r] = fmaf(w, b, a); u[r + 1] = fmaf(-w, b, a);
    }
    __syncthreads();
    // keep only bit11=0 half (addrs < 2048 at depth 5): addr = h + 256*brev3(j)
    #pragma unroll
    for (int j = 0; j < 8; j++) {
        int c = ((j & 1) << 2) | (j & 2) | ((j & 4) >> 2);
        buf[h + (c << 8)] = u[2 * j];
    }
    __syncthreads();

    // pruned levels t=4..0 (keep k<64)
    float* src = buf; float* dst = buf + 2048;
    #pragma unroll
    for (int t = 4; t >= 0; t--) {
        int count = MODES << t;
        for (int i = h; i < count; i += 256) {
            int p = i & ((1 << t) - 1), k = i >> t;
            dst[p + (k << t)] =
                fmaf(cas1k[k << t], src[p + (1 << t) + (k << (t + 1))],
                     src[p + (k << (t + 1))]);
        }
        float* tp = src; src = dst; dst = tp;
        __syncthreads();
    }
    if (h < 64) g_Y[h * ROWS + row] = src[h];
}

// ---------------- mix ----------------
// grid = 256 (64 modes x 4 quarters of 16 batches), 256 threads.
// thread: 2 batches x 4 outputs; weights via coalesced LDG.128.
__global__ __launch_bounds__(256) void mix_kernel() {
    __shared__ float Ys[16 * CH];
    __shared__ float Yn[16 * CH];
    int m = blockIdx.x >> 2, q = blockIdx.x & 3;
    int mn = (MODES - m) & (MODES - 1);
    int tid = threadIdx.x;
    int base = q * 2048;
    for (int idx = tid; idx < 2048; idx += 256) {
        Ys[idx] = g_Y[m * ROWS + base + idx];
        Yn[idx] = g_Y[mn * ROWS + base + idx];
    }
    __syncthreads();

    int oq = tid & 31, bp = tid >> 5;
    int l0 = 2 * bp, l1 = l0 + 1;
    float a00 = 0, a01 = 0, a02 = 0, a03 = 0;
    float a10 = 0, a11 = 0, a12 = 0, a13 = 0;
    const float4* We4 = (const float4*)(g_We + (size_t)m * CH * CH);
    const float4* Wo4 = (const float4*)(g_Wo + (size_t)m * CH * CH);

    #pragma unroll 4
    for (int i = 0; i < CH; i++) {
        float4 we = We4[i * 32 + oq];
        float4 wo = Wo4[i * 32 + oq];
        float y0 = Ys[l0 * CH + i], y1 = Ys[l1 * CH + i];
        float z0 = Yn[l0 * CH + i], z1 = Yn[l1 * CH + i];
        a00 = fmaf(y0, we.x, a00); a00 = fmaf(z0, wo.x, a00);
        a01 = fmaf(y0, we.y, a01); a01 = fmaf(z0, wo.y, a01);
        a02 = fmaf(y0, we.z, a02); a02 = fmaf(z0, wo.z, a02);
        a03 = fmaf(y0, we.w, a03); a03 = fmaf(z0, wo.w, a03);
        a10 = fmaf(y1, we.x, a10); a10 = fmaf(z1, wo.x, a10);
        a11 = fmaf(y1, we.y, a11); a11 = fmaf(z1, wo.y, a11);
        a12 = fmaf(y1, we.z, a12); a12 = fmaf(z1, wo.z, a12);
        a13 = fmaf(y1, we.w, a13); a13 = fmaf(z1, wo.w, a13);
    }
    const float inv = 1.0f / 4096.0f;
    int b0 = q * 16 + l0, b1 = q * 16 + l1, o = oq * 4;
    g_Z[((size_t)(b0 * CH + o    )) * MODES + m] = a00 * inv;
    g_Z[((size_t)(b0 * CH + o + 1)) * MODES + m] = a01 * inv;
    g_Z[((size_t)(b0 * CH + o + 2)) * MODES + m] = a02 * inv;
    g_Z[((size_t)(b0 * CH + o + 3)) * MODES + m] = a03 * inv;
    g_Z[((size_t)(b1 * CH + o    )) * MODES + m] = a10 * inv;
    g_Z[((size_t)(b1 * CH + o + 1)) * MODES + m] = a11 * inv;
    g_Z[((size_t)(b1 * CH + o + 2)) * MODES + m] = a12 * inv;
    g_Z[((size_t)(b1 * CH + o + 3)) * MODES + m] = a13 * inv;
}

// ---------------- inverse ----------------
__global__ __launch_bounds__(256) void inverse_kernel(float* __restrict__ out) {
    __shared__ float buf[4096];
    __shared__ float cas_s[2048];
    __shared__ float zb[64];
    int h = threadIdx.x, row = blockIdx.x;

    for (int j = h; j < 2048; j += 256) cas_s[j] = g_CAS[j];
    if (h < 64) zb[h] = g_Z[((size_t)row << 6) + h];
    __syncthreads();

    // init (depth-6): addr&63 = (h&7) + 8*rb0 + 16*rb1 + 32*rb2; bit11 free
    float v[16];
    #pragma unroll
    for (int r = 0; r < 16; r++) v[r] = zb[(h & 7) + ((r & 7) << 3)];

    int hk = (h >> 3) & 31;
    // t=5: kt = hk + 32*rb3
    #pragma unroll
    for (int r = 0; r < 16; r++) if (!(r & 4)) {
        float w = cas_s[(hk + ((r & 8) << 2)) << 5];
        float a = v[r], b = v[r + 4];
        v[r] = fmaf(w, b, a); v[r + 4] = fmaf(-w, b, a);
    }
    // t=4: kt = hk + 32*rb3 + 64*rb2
    #pragma unroll
    for (int r = 0; r < 16; r++) if (!(r & 2)) {
        float w = cas_s[(hk + ((r & 8) << 2) + ((r & 4) << 4)) << 4];
        float a = v[r], b = v[r + 2];
        v[r] = fmaf(w, b, a); v[r + 2] = fmaf(-w, b, a);
    }
    // t=3: kt = hk + 32*rb3 + 64*rb2 + 128*rb1
    #pragma unroll
    for (int r = 0; r < 16; r += 2) {
        float w = cas_s[(hk + ((r & 8) << 2) + ((r & 4) << 4) + ((r & 2) << 6)) << 3];
        float a = v[r], b = v[r + 1];
        v[r] = fmaf(w, b, a); v[r + 1] = fmaf(-w, b, a);
    }

    // exchange (swizzled: phys = a ^ ((a>>5)&7), conflict-free both directions)
    #pragma unroll
    for (int r = 0; r < 16; r++) {
        int a = h + (brev4(r) << 8);
        buf[a ^ ((a >> 5) & 7)] = v[r];
    }
    __syncthreads();
    #pragma unroll
    for (int r = 0; r < 16; r++) {
        int a = (r & 7) + (h << 3) + ((r & 8) << 8);
        v[r] = buf[a ^ ((a >> 5) & 7)];
    }

    // t=2: kt = h + 256*rb3
    #pragma unroll
    for (int r = 0; r < 16; r++) if (!(r & 4)) {
        float w = cas_s[(h + ((r & 8) << 5)) << 2];
        float a = v[r], b = v[r + 4];
        v[r] = fmaf(w, b, a); v[r + 4] = fmaf(-w, b, a);
    }
    // t=1: kt = h + 256*rb3 + 512*rb2
    #pragma unroll
    for (int r = 0; r < 16; r++) if (!(r & 2)) {
        float w = cas_s[(h + ((r & 8) << 5) + ((r & 4) << 7)) << 1];
        float a = v[r], b = v[r + 2];
        v[r] = fmaf(w, b, a); v[r + 2] = fmaf(-w, b, a);
    }
    // t=0: kt = h + 256*rb3 + 512*rb2 + 1024*rb1
    #pragma unroll
    for (int r = 0; r < 16; r += 2) {
        float w = cas_s[h + ((r & 8) << 5) + ((r & 4) << 7) + ((r & 2) << 9)];
        float a = v[r], b = v[r + 1];
        v[r] = fmaf(w, b, a); v[r + 1] = fmaf(-w, b, a);
    }

    // stage output through smem (plain layout) -> coalesced float4 stores
    __syncthreads();
    #pragma unroll
    for (int r = 0; r < 16; r++) buf[h + (brev4(r) << 8)] = v[r];
    __syncthreads();

    float4* o4 = (float4*)(out + (size_t)row * NN);
    const float4* s4 = (const float4*)buf;
    #pragma unroll
    for (int k = 0; k < 4; k++) o4[h + (k << 8)] = s4[h + (k << 8)];
}

extern "C" void kernel_launch(void* const* d_in, const int* in_sizes, int n_in,
                              void* d_out, int out_size) {
    const float* x  = (const float*)d_in[0];
    const float* w1 = (const float*)d_in[1];
    float* out = (float*)d_out;

    build_cas_kernel<<<8, 256>>>();
    build_wewo_kernel<<<(MODES * CH * CH + 511) / 512, 512>>>(w1);
    forward_kernel<<<ROWS, 256>>>(x);
    mix_kernel<<<MODES * 4, 256>>>();
    inverse_kernel<<<ROWS, 256>>>(out);
}

// round 5
// speedup vs baseline: 1.9803x; 1.8457x over previous
#include <cuda_runtime.h>
#include <cstdint>

// SpectralConv1d via pruned cas-FFT.
// forward: 4 reg levels -> 1 smem exchange -> 3 reg levels (even-only at t=5)
//          -> omega-weighted warp shfl reductions (no barriers, no smem tail)
// mix:     cp.async double-buffered weight tiles, 16 accums/thread
// inverse: unchanged from R3 (broadcast init, reg levels, swizzled exchange)

#define NN     4096
#define MODES  64
#define CH     128
#define ROWS   8192

#define SQ2   1.41421356237309515f
#define C256  1.30656296487637653f   // cas(pi/8)
#define C1280 0.54119610014619698f   // cas(5pi/8)

__device__ float g_CAS[2048];             // cas(2*pi*j/4096)
__device__ float g_OM[2048];              // omega[k<64][q<32]
__device__ float g_Y[MODES * ROWS];       // [m][row]
__device__ float g_Z[ROWS * MODES];       // [row][m] (already /4096)
__device__ float g_We[MODES * CH * CH];   // [m][i][o]
__device__ float g_Wo[MODES * CH * CH];   // [m][i][o]

__global__ void build_tables_kernel() {
    int j = blockIdx.x * blockDim.x + threadIdx.x;
    if (j < 2048) {
        float s, c;
        sincospif((float)j * (1.0f / 2048.0f), &s, &c);
        g_CAS[j] = c + s;
    } else if (j < 4096) {
        int idx = j - 2048;
        int k = idx >> 5, q = idx & 31;
        float w = 1.0f;
        #pragma unroll
        for (int t = 0; t < 5; t++) {
            if ((q >> t) & 1) {
                float s, c;
                sincospif((float)(k << t) * (1.0f / 2048.0f), &s, &c);
                w *= (c + s);
            }
        }
        g_OM[idx] = w;
    }
}

__global__ void build_wewo_kernel(const float* __restrict__ w1) {
    int t = blockIdx.x * blockDim.x + threadIdx.x;
    if (t >= MODES * CH * CH) return;
    int m   = t >> 14;
    int rem = t & 16383;
    int i   = rem >> 7;
    int o   = rem & 127;
    int mn  = (MODES - m) & (MODES - 1);
    float a = w1[i * (CH * MODES) + o * MODES + m];
    float b = w1[i * (CH * MODES) + o * MODES + mn];
    g_We[t] = 0.5f * (a + b);
    g_Wo[t] = 0.5f * (a - b);
}

__device__ __forceinline__ int brev4(int r) {
    return ((r & 1) << 3) | ((r & 2) << 1) | ((r & 4) >> 1) | ((r & 8) >> 3);
}

// ---------------- forward ----------------
__global__ __launch_bounds__(256) void forward_kernel(const float* __restrict__ x) {
    __shared__ float buf[4096];
    __shared__ float cas32s[64];
    int h = threadIdx.x, row = blockIdx.x;
    int lane = h & 31, wrp = h >> 5;

    if (h < 64) cas32s[h] = g_CAS[h << 5];

    const float* xr = x + (size_t)row * NN;
    float v[16];
    #pragma unroll
    for (int r = 0; r < 16; r++) v[r] = xr[h + (r << 8)];

    // preload omega rows for the tail (k = wrp + 8c, q = lane) — coalesced
    float om[8];
    #pragma unroll
    for (int c = 0; c < 8; c++) om[c] = g_OM[((wrp + (c << 3)) << 5) + lane];

    // stage 1: levels t=11,10 (tw=1), t=9, t=8 — const twiddles
    #pragma unroll
    for (int r = 0; r < 8; r++) { float a = v[r], b = v[r + 8]; v[r] = a + b; v[r + 8] = a - b; }
    #pragma unroll
    for (int r = 0; r < 16; r++) if (!(r & 4)) { float a = v[r], b = v[r + 4]; v[r] = a + b; v[r + 4] = a - b; }
    {
        const float TW9[4] = {1.f, SQ2, 1.f, 0.f};
        #pragma unroll
        for (int r = 0; r < 16; r++) if (!(r & 2)) {
            int kt = ((r >> 3) & 1) | (((r >> 2) & 1) << 1);
            float w = TW9[kt], a = v[r], b = v[r + 2];
            v[r] = fmaf(w, b, a); v[r + 2] = fmaf(-w, b, a);
        }
    }
    {
        const float TW8[8] = {1.f, C256, SQ2, C256, 1.f, C1280, 0.f, -C1280};
        #pragma unroll
        for (int r = 0; r < 16; r += 2) {
            int kt = ((r >> 3) & 1) | (((r >> 2) & 1) << 1) | (((r >> 1) & 1) << 2);
            float w = TW8[kt], a = v[r], b = v[r + 1];
            v[r] = fmaf(w, b, a); v[r + 1] = fmaf(-w, b, a);
        }
    }
    // exchange (depth-8 layout)
    #pragma unroll
    for (int r = 0; r < 16; r++) buf[h + (brev4(r) << 8)] = v[r];
    __syncthreads();

    // stage 2: free bits {5,6,7,11}
    int hi3 = wrp;
    int base = (h & 31) + (hi3 << 8);
    float u[16];
    #pragma unroll
    for (int r = 0; r < 16; r++) u[r] = buf[base + ((r & 7) << 5) + ((r & 8) << 8)];
    // t=7
    #pragma unroll
    for (int r = 0; r < 16; r++) if (!(r & 4)) {
        float w = cas32s[(hi3 + (r & 8)) << 2];
        float a = u[r], b = u[r + 4];
        u[r] = fmaf(w, b, a); u[r + 4] = fmaf(-w, b, a);
    }
    // t=6
    #pragma unroll
    for (int r = 0; r < 16; r++) if (!(r & 2)) {
        float w = cas32s[(hi3 + (r & 8) + ((r & 4) << 2)) << 1];
        float a = u[r], b = u[r + 2];
        u[r] = fmaf(w, b, a); u[r + 2] = fmaf(-w, b, a);
    }
    // t=5: only even outputs survive the k<64 prune
    #pragma unroll
    for (int r = 0; r < 16; r += 2) {
        float w = cas32s[hi3 + (r & 8) + ((r & 4) << 2) + ((r & 2) << 4)];
        u[r] = fmaf(w, u[r + 1], u[r]);
    }

    // tail: Y[k] = sum_q omega[k,q] * D5[32k+q]; chunk k lives on one warp.
    // value u[2*brev3(c)] at lane q corresponds to (k = wrp + 8c, q = lane).
    float res = 0.0f;
    #pragma unroll
    for (int c = 0; c < 8; c++) {
        int j = ((c & 1) << 2) | (c & 2) | ((c & 4) >> 2);  // brev3(c)
        float val = om[c] * u[2 * j];
        val += __shfl_xor_sync(0xffffffffu, val, 16);
        val += __shfl_xor_sync(0xffffffffu, val, 8);
        val += __shfl_xor_sync(0xffffffffu, val, 4);
        val += __shfl_xor_sync(0xffffffffu, val, 2);
        val += __shfl_xor_sync(0xffffffffu, val, 1);
        if (lane == c) res = val;
    }
    if (lane < 8) g_Y[(wrp + (lane << 3)) * ROWS + row] = res;
}

// ---------------- mix ----------------
// grid = 256 (64 modes x 4 quarters of 16 batches), 128 threads.
// thread (oq = tid&31, bg = tid>>5): 4 batches x 4 outputs, 16 accums.
// Weights streamed in 16-i chunks, double-buffered via cp.async.
__device__ __forceinline__ void cp16(uint32_t daddr, const void* gptr) {
    asm volatile("cp.async.cg.shared.global [%0], [%1], 16;" :: "r"(daddr), "l"(gptr));
}

__global__ __launch_bounds__(128) void mix_kernel() {
    __shared__ float Ys[16 * CH];
    __shared__ float Yn[16 * CH];
    extern __shared__ float4 Wbuf[];   // [2 stages][2 mats][512 float4] = 32KB

    int m = blockIdx.x >> 2, q = blockIdx.x & 3;
    int mn = (MODES - m) & 63;
    int tid = threadIdx.x;
    int oq = tid & 31, bg = tid >> 5;

    const float* We = g_We + (size_t)m * 16384;
    const float* Wo = g_Wo + (size_t)m * 16384;
    uint32_t wb = (uint32_t)__cvta_generic_to_shared(Wbuf);

    // issue chunk c into stage s: 16 i-rows x 128 o of We and Wo (8 cp.async/thread)
    #define ISSUE_CHUNK(c, s) do {                                              \
        const float4* se = (const float4*)(We + (c) * 2048);                    \
        const float4* so = (const float4*)(Wo + (c) * 2048);                    \
        uint32_t de = wb + (uint32_t)((s) * 2 + 0) * 8192;                      \
        uint32_t dn = wb + (uint32_t)((s) * 2 + 1) * 8192;                      \
        _Pragma("unroll")                                                       \
        for (int jj = 0; jj < 4; jj++) {                                        \
            int idx = tid + jj * 128;                                           \
            cp16(de + idx * 16, se + idx);                                      \
            cp16(dn + idx * 16, so + idx);                                      \
        }                                                                       \
        asm volatile("cp.async.commit_group;" ::: "memory");                    \
    } while (0)

    ISSUE_CHUNK(0, 0);
    ISSUE_CHUNK(1, 1);

    for (int idx = tid; idx < 2048; idx += 128) {
        Ys[idx] = g_Y[m * ROWS + q * 2048 + idx];
        Yn[idx] = g_Y[mn * ROWS + q * 2048 + idx];
    }

    float4 a0 = {0,0,0,0}, a1 = {0,0,0,0}, a2 = {0,0,0,0}, a3 = {0,0,0,0};

    #pragma unroll 1
    for (int c = 0; c < 8; c++) {
        if (c < 7) asm volatile("cp.async.wait_group 1;" ::: "memory");
        else       asm volatile("cp.async.wait_group 0;" ::: "memory");
        __syncthreads();

        const float4* Wef = &Wbuf[(size_t)((c & 1) * 2 + 0) * 512];
        const float4* Wof = &Wbuf[(size_t)((c & 1) * 2 + 1) * 512];
        #pragma unroll
        for (int ii = 0; ii < 16; ii++) {
            float4 we = Wef[ii * 32 + oq];
            float4 wo = Wof[ii * 32 + oq];
            int i = c * 16 + ii;
            float y0 = Ys[(bg * 4 + 0) * CH + i], z0 = Yn[(bg * 4 + 0) * CH + i];
            float y1 = Ys[(bg * 4 + 1) * CH + i], z1 = Yn[(bg * 4 + 1) * CH + i];
            float y2 = Ys[(bg * 4 + 2) * CH + i], z2 = Yn[(bg * 4 + 2) * CH + i];
            float y3 = Ys[(bg * 4 + 3) * CH + i], z3 = Yn[(bg * 4 + 3) * CH + i];
            a0.x = fmaf(y0, we.x, a0.x); a0.x = fmaf(z0, wo.x, a0.x);
            a0.y = fmaf(y0, we.y, a0.y); a0.y = fmaf(z0, wo.y, a0.y);
            a0.z = fmaf(y0, we.z, a0.z); a0.z = fmaf(z0, wo.z, a0.z);
            a0.w = fmaf(y0, we.w, a0.w); a0.w = fmaf(z0, wo.w, a0.w);
            a1.x = fmaf(y1, we.x, a1.x); a1.x = fmaf(z1, wo.x, a1.x);
            a1.y = fmaf(y1, we.y, a1.y); a1.y = fmaf(z1, wo.y, a1.y);
            a1.z = fmaf(y1, we.z, a1.z); a1.z = fmaf(z1, wo.z, a1.z);
            a1.w = fmaf(y1, we.w, a1.w); a1.w = fmaf(z1, wo.w, a1.w);
            a2.x = fmaf(y2, we.x, a2.x); a2.x = fmaf(z2, wo.x, a2.x);
            a2.y = fmaf(y2, we.y, a2.y); a2.y = fmaf(z2, wo.y, a2.y);
            a2.z = fmaf(y2, we.z, a2.z); a2.z = fmaf(z2, wo.z, a2.z);
            a2.w = fmaf(y2, we.w, a2.w); a2.w = fmaf(z2, wo.w, a2.w);
            a3.x = fmaf(y3, we.x, a3.x); a3.x = fmaf(z3, wo.x, a3.x);
            a3.y = fmaf(y3, we.y, a3.y); a3.y = fmaf(z3, wo.y, a3.y);
            a3.z = fmaf(y3, we.z, a3.z); a3.z = fmaf(z3, wo.z, a3.z);
            a3.w = fmaf(y3, we.w, a3.w); a3.w = fmaf(z3, wo.w, a3.w);
        }
        __syncthreads();
        if (c < 6) ISSUE_CHUNK(c + 2, c & 1);
    }

    const float inv = 1.0f / 4096.0f;
    int b0 = q * 16 + bg * 4;
    int o = oq * 4;
    float4 accs[4] = {a0, a1, a2, a3};
    #pragma unroll
    for (int bb = 0; bb < 4; bb++) {
        size_t zb = ((size_t)((b0 + bb) * CH + o)) * MODES + m;
        g_Z[zb]       = accs[bb].x * inv;
        g_Z[zb + 64]  = accs[bb].y * inv;
        g_Z[zb + 128] = accs[bb].z * inv;
        g_Z[zb + 192] = accs[bb].w * inv;
    }
    #undef ISSUE_CHUNK
}

// ---------------- inverse (unchanged from R3) ----------------
__global__ __launch_bounds__(256) void inverse_kernel(float* __restrict__ out) {
    __shared__ float buf[4096];
    __shared__ float cas_s[2048];
    __shared__ float zb[64];
    int h = threadIdx.x, row = blockIdx.x;

    for (int j = h; j < 2048; j += 256) cas_s[j] = g_CAS[j];
    if (h < 64) zb[h] = g_Z[((size_t)row << 6) + h];
    __syncthreads();

    float v[16];
    #pragma unroll
    for (int r = 0; r < 16; r++) v[r] = zb[(h & 7) + ((r & 7) << 3)];

    int hk = (h >> 3) & 31;
    #pragma unroll
    for (int r = 0; r < 16; r++) if (!(r & 4)) {
        float w = cas_s[(hk + ((r & 8) << 2)) << 5];
        float a = v[r], b = v[r + 4];
        v[r] = fmaf(w, b, a); v[r + 4] = fmaf(-w, b, a);
    }
    #pragma unroll
    for (int r = 0; r < 16; r++) if (!(r & 2)) {
        float w = cas_s[(hk + ((r & 8) << 2) + ((r & 4) << 4)) << 4];
        float a = v[r], b = v[r + 2];
        v[r] = fmaf(w, b, a); v[r + 2] = fmaf(-w, b, a);
    }
    #pragma unroll
    for (int r = 0; r < 16; r += 2) {
        float w = cas_s[(hk + ((r & 8) << 2) + ((r & 4) << 4) + ((r & 2) << 6)) << 3];
        float a = v[r], b = v[r + 1];
        v[r] = fmaf(w, b, a); v[r + 1] = fmaf(-w, b, a);
    }

    #pragma unroll
    for (int r = 0; r < 16; r++) {
        int a = h + (brev4(r) << 8);
        buf[a ^ ((a >> 5) & 7)] = v[r];
    }
    __syncthreads();
    #pragma unroll
    for (int r = 0; r < 16; r++) {
        int a = (r & 7) + (h << 3) + ((r & 8) << 8);
        v[r] = buf[a ^ ((a >> 5) & 7)];
    }

    #pragma unroll
    for (int r = 0; r < 16; r++) if (!(r & 4)) {
        float w = cas_s[(h + ((r & 8) << 5)) << 2];
        float a = v[r], b = v[r + 4];
        v[r] = fmaf(w, b, a); v[r + 4] = fmaf(-w, b, a);
    }
    #pragma unroll
    for (int r = 0; r < 16; r++) if (!(r & 2)) {
        float w = cas_s[(h + ((r & 8) << 5) + ((r & 4) << 7)) << 1];
        float a = v[r], b = v[r + 2];
        v[r] = fmaf(w, b, a); v[r + 2] = fmaf(-w, b, a);
    }
    #pragma unroll
    for (int r = 0; r < 16; r += 2) {
        float w = cas_s[h + ((r & 8) << 5) + ((r & 4) << 7) + ((r & 2) << 9)];
        float a = v[r], b = v[r + 1];
        v[r] = fmaf(w, b, a); v[r + 1] = fmaf(-w, b, a);
    }

    __syncthreads();
    #pragma unroll
    for (int r = 0; r < 16; r++) buf[h + (brev4(r) << 8)] = v[r];
    __syncthreads();

    float4* o4 = (float4*)(out + (size_t)row * NN);
    const float4* s4 = (const float4*)buf;
    #pragma unroll
    for (int k = 0; k < 4; k++) o4[h + (k << 8)] = s4[h + (k << 8)];
}

extern "C" void kernel_launch(void* const* d_in, const int* in_sizes, int n_in,
                              void* d_out, int out_size) {
    const float* x  = (const float*)d_in[0];
    const float* w1 = (const float*)d_in[1];
    float* out = (float*)d_out;

    build_tables_kernel<<<16, 256>>>();
    build_wewo_kernel<<<(MODES * CH * CH + 511) / 512, 512>>>(w1);
    forward_kernel<<<ROWS, 256>>>(x);
    mix_kernel<<<MODES * 4, 128, 32768>>>();
    inverse_kernel<<<ROWS, 256>>>(out);
}